// round 1
// baseline (speedup 1.0000x reference)
#include <cuda_runtime.h>

// SSIM loss: 1 - mean(ssim_map(clean, adv)), 11x11 gaussian sigma=1.5, zero ("valid"-style SAME) padding.
// Inputs: d_in[0]=clean [32,3,512,512] f32, d_in[1]=adversarial same. Output: 1 float.

#define IMG 512
#define TILE 32
#define HALO 5
#define EXT (TILE + 2 * HALO) // 42
#define NPLANES (32 * 3)
#define NPIX (32.0 * 3.0 * 512.0 * 512.0)

__device__ double g_ssim_acc;

// Gaussian window weights, sigma=1.5, size 11, normalized (precomputed high precision)
#define W0 0.26601173f
#define W1 0.21300555f
#define W2 0.10936069f
#define W3 0.03600077f
#define W4 0.00759875f
#define W5 0.00102838f

__global__ void zero_acc_kernel() { g_ssim_acc = 0.0; }

__global__ void __launch_bounds__(256) ssim_tile_kernel(
    const float* __restrict__ clean, const float* __restrict__ adv)
{
    // packed (clean, adv) halo tile
    __shared__ float2 s_ca[EXT][EXT];        // 42*42*8  = 14112 B
    // horizontal-pass intermediates
    __shared__ float2 s_mu[EXT][TILE];       // (m1, m2)   10752 B
    __shared__ float2 s_sq[EXT][TILE];       // (s11, s22) 10752 B
    __shared__ float  s_xx[EXT][TILE];       // s12         5376 B
    __shared__ float  s_red[8];

    const float w[11] = {W5, W4, W3, W2, W1, W0, W1, W2, W3, W4, W5};

    const int plane = blockIdx.z;
    const float* cp = clean + (size_t)plane * IMG * IMG;
    const float* ap = adv   + (size_t)plane * IMG * IMG;
    const int x0 = blockIdx.x * TILE;
    const int y0 = blockIdx.y * TILE;
    const int tid = threadIdx.x;

    // ---- load halo tile (zero padding outside image) ----
    #pragma unroll 2
    for (int idx = tid; idx < EXT * EXT; idx += 256) {
        int r = idx / EXT, c = idx - r * EXT;
        int gy = y0 - HALO + r;
        int gx = x0 - HALO + c;
        float cv = 0.f, av = 0.f;
        if ((unsigned)gy < IMG && (unsigned)gx < IMG) {
            cv = cp[gy * IMG + gx];
            av = ap[gy * IMG + gx];
        }
        s_ca[r][c] = make_float2(cv, av);
    }
    __syncthreads();

    // ---- horizontal pass: 42 rows x 32 cols of 5 windowed sums ----
    for (int idx = tid; idx < EXT * TILE; idx += 256) {
        int r = idx >> 5, c = idx & 31;
        float m1 = 0.f, m2 = 0.f, s11 = 0.f, s22 = 0.f, s12 = 0.f;
        #pragma unroll
        for (int k = 0; k < 11; k++) {
            float2 v = s_ca[r][c + k];
            float t = w[k] * v.x;
            float u = w[k] * v.y;
            m1 += t;
            m2 += u;
            s11 = fmaf(t, v.x, s11);
            s22 = fmaf(u, v.y, s22);
            s12 = fmaf(t, v.y, s12);
        }
        s_mu[r][c] = make_float2(m1, m2);
        s_sq[r][c] = make_float2(s11, s22);
        s_xx[r][c] = s12;
    }
    __syncthreads();

    // ---- vertical pass + SSIM epilogue: 32x32 outputs, 4 per thread ----
    const float C1 = 1.0e-4f;   // 0.01^2
    const float C2 = 9.0e-4f;   // 0.03^2
    const int tx = tid & 31;
    const int tyb = tid >> 5;   // 0..7
    float local = 0.f;
    #pragma unroll
    for (int rr = 0; rr < 4; rr++) {
        int r = tyb + rr * 8;
        float m1 = 0.f, m2 = 0.f, e11 = 0.f, e22 = 0.f, e12 = 0.f;
        #pragma unroll
        for (int k = 0; k < 11; k++) {
            float2 m = s_mu[r + k][tx];
            float2 s = s_sq[r + k][tx];
            float  x = s_xx[r + k][tx];
            m1  = fmaf(w[k], m.x, m1);
            m2  = fmaf(w[k], m.y, m2);
            e11 = fmaf(w[k], s.x, e11);
            e22 = fmaf(w[k], s.y, e22);
            e12 = fmaf(w[k], x,   e12);
        }
        float mu1_sq = m1 * m1;
        float mu2_sq = m2 * m2;
        float mu12   = m1 * m2;
        float sig1 = e11 - mu1_sq;
        float sig2 = e22 - mu2_sq;
        float sig12 = e12 - mu12;
        float num = (2.f * mu12 + C1) * (2.f * sig12 + C2);
        float den = (mu1_sq + mu2_sq + C1) * (sig1 + sig2 + C2);
        local += num / den;
    }

    // ---- block reduction ----
    #pragma unroll
    for (int off = 16; off > 0; off >>= 1)
        local += __shfl_down_sync(0xFFFFFFFFu, local, off);
    if (tx == 0) s_red[tyb] = local;
    __syncthreads();
    if (tid == 0) {
        float bs = 0.f;
        #pragma unroll
        for (int i = 0; i < 8; i++) bs += s_red[i];
        atomicAdd(&g_ssim_acc, (double)bs);
    }
}

__global__ void finalize_kernel(float* out) {
    out[0] = 1.0f - (float)(g_ssim_acc / NPIX);
}

extern "C" void kernel_launch(void* const* d_in, const int* in_sizes, int n_in,
                              void* d_out, int out_size) {
    const float* clean = (const float*)d_in[0];
    const float* adv   = (const float*)d_in[1];
    float* out = (float*)d_out;

    zero_acc_kernel<<<1, 1>>>();
    dim3 grid(IMG / TILE, IMG / TILE, NPLANES);
    ssim_tile_kernel<<<grid, 256>>>(clean, adv);
    finalize_kernel<<<1, 1>>>(out);
}

// round 2
// speedup vs baseline: 1.2804x; 1.2804x over previous
#include <cuda_runtime.h>

// SSIM loss: 1 - mean(ssim_map(clean, adv)), 11x11 gaussian sigma=1.5, zero SAME padding.
// d_in[0]=clean [32,3,512,512] f32, d_in[1]=adversarial. Output: 1 float.

#define IMG 512
#define TILE 32
#define HALO 5
#define EXT (TILE + 2 * HALO)   // 42
#define NPLANES (32 * 3)
#define NPIX (32.0 * 3.0 * 512.0 * 512.0)

typedef unsigned long long u64;

__device__ double g_ssim_acc = 0.0;

// ---- packed f32x2 helpers (ptxas will not emit FFMA2 from C++) ----
__device__ __forceinline__ u64 pack2(float x, float y) {
    u64 r; asm("mov.b64 %0, {%1, %2};" : "=l"(r) : "f"(x), "f"(y)); return r;
}
__device__ __forceinline__ float2 un2(u64 v) {
    float2 r; asm("mov.b64 {%0, %1}, %2;" : "=f"(r.x), "=f"(r.y) : "l"(v)); return r;
}
__device__ __forceinline__ u64 fma2(u64 a, u64 b, u64 c) {
    u64 d; asm("fma.rn.f32x2 %0, %1, %2, %3;" : "=l"(d) : "l"(a), "l"(b), "l"(c)); return d;
}
__device__ __forceinline__ u64 mul2(u64 a, u64 b) {
    u64 d; asm("mul.rn.f32x2 %0, %1, %2;" : "=l"(d) : "l"(a), "l"(b)); return d;
}
__device__ __forceinline__ u64 add2(u64 a, u64 b) {
    u64 d; asm("add.rn.f32x2 %0, %1, %2;" : "=l"(d) : "l"(a), "l"(b)); return d;
}

// Gaussian window, sigma=1.5, 11 taps, normalized.
#define W0 0.26601173f
#define W1 0.21300555f
#define W2 0.10936069f
#define W3 0.03600077f
#define W4 0.00759875f
#define W5 0.00102838f

__global__ void __launch_bounds__(256) ssim_tile_kernel(
    const float* __restrict__ clean, const float* __restrict__ adv)
{
    __shared__ u64 s_ca[EXT][EXT];        // packed (clean, adv)      14112 B
    __shared__ u64 s_mu[EXT][TILE];       // packed (m1, m2)          10752 B
    __shared__ u64 s_sq[EXT][TILE];       // packed (s11, s22)        10752 B
    __shared__ float s_xx[EXT][TILE];     // s12                       5376 B
    __shared__ float s_red[8];

    const float wf[11] = {W5, W4, W3, W2, W1, W0, W1, W2, W3, W4, W5};
    u64 wp[11];
    #pragma unroll
    for (int k = 0; k < 11; k++) wp[k] = pack2(wf[k], wf[k]);

    const int plane = blockIdx.z;
    const float* cp = clean + (size_t)plane * IMG * IMG;
    const float* ap = adv   + (size_t)plane * IMG * IMG;
    const int x0 = blockIdx.x * TILE;
    const int y0 = blockIdx.y * TILE;
    const int tid = threadIdx.x;

    // ---- load halo tile (zero padding outside image) ----
    #pragma unroll 2
    for (int idx = tid; idx < EXT * EXT; idx += 256) {
        int r = idx / EXT, c = idx - r * EXT;
        int gy = y0 - HALO + r;
        int gx = x0 - HALO + c;
        float cv = 0.f, av = 0.f;
        if ((unsigned)gy < IMG && (unsigned)gx < IMG) {
            cv = cp[gy * IMG + gx];
            av = ap[gy * IMG + gx];
        }
        s_ca[r][c] = pack2(cv, av);
    }
    __syncthreads();

    // ---- horizontal pass: 42 rows x 32 cols, packed accumulators ----
    for (int idx = tid; idx < EXT * TILE; idx += 256) {
        int r = idx >> 5, c = idx & 31;
        const u64* row = &s_ca[r][c];
        u64 m = 0ull, s = 0ull;
        float s12 = 0.f;
        #pragma unroll
        for (int k = 0; k < 11; k++) {
            u64 v = row[k];
            u64 t = mul2(wp[k], v);          // (w*x, w*y)
            m = add2(m, t);                  // (mu1, mu2)
            s = fma2(t, v, s);               // (E x^2, E y^2)
            float2 tv = un2(t);
            float2 vv = un2(v);
            s12 = fmaf(tv.x, vv.y, s12);     // E xy
        }
        s_mu[r][c] = m;
        s_sq[r][c] = s;
        s_xx[r][c] = s12;
    }
    __syncthreads();

    // ---- vertical pass: each thread computes 4 CONSECUTIVE rows,
    //      loading the 15 covering intermediate rows exactly once ----
    const float C1 = 1.0e-4f;
    const float C2 = 9.0e-4f;
    const int tx = tid & 31;
    const int ty = tid >> 5;        // 0..7
    const int rbase = ty * 4;       // output rows rbase..rbase+3

    u64 am[4] = {0ull, 0ull, 0ull, 0ull};
    u64 ae[4] = {0ull, 0ull, 0ull, 0ull};
    float a12[4] = {0.f, 0.f, 0.f, 0.f};

    #pragma unroll
    for (int j = 0; j < 15; j++) {
        int r = rbase + j;
        u64 mu = s_mu[r][tx];
        u64 sq = s_sq[r][tx];
        float xx = s_xx[r][tx];
        #pragma unroll
        for (int o = 0; o < 4; o++) {
            const int k = j - o;
            if (k >= 0 && k <= 10) {
                am[o] = fma2(wp[k], mu, am[o]);
                ae[o] = fma2(wp[k], sq, ae[o]);
                a12[o] = fmaf(wf[k], xx, a12[o]);
            }
        }
    }

    float local = 0.f;
    #pragma unroll
    for (int o = 0; o < 4; o++) {
        float2 m = un2(am[o]);
        float2 e = un2(ae[o]);
        float mu1_sq = m.x * m.x;
        float mu2_sq = m.y * m.y;
        float mu12   = m.x * m.y;
        float sig1  = e.x - mu1_sq;
        float sig2  = e.y - mu2_sq;
        float sig12 = a12[o] - mu12;
        float num = (2.f * mu12 + C1) * (2.f * sig12 + C2);
        float den = (mu1_sq + mu2_sq + C1) * (sig1 + sig2 + C2);
        local += __fdividef(num, den);
    }

    // ---- block reduction ----
    #pragma unroll
    for (int off = 16; off > 0; off >>= 1)
        local += __shfl_down_sync(0xFFFFFFFFu, local, off);
    if (tx == 0) s_red[ty] = local;
    __syncthreads();
    if (tid == 0) {
        float bs = 0.f;
        #pragma unroll
        for (int i = 0; i < 8; i++) bs += s_red[i];
        atomicAdd(&g_ssim_acc, (double)bs);
    }
}

// Reads the accumulator, writes the loss, and resets the accumulator so the
// next graph replay starts from zero (deterministic across replays).
__global__ void finalize_kernel(float* out) {
    out[0] = 1.0f - (float)(g_ssim_acc / NPIX);
    g_ssim_acc = 0.0;
}

extern "C" void kernel_launch(void* const* d_in, const int* in_sizes, int n_in,
                              void* d_out, int out_size) {
    const float* clean = (const float*)d_in[0];
    const float* adv   = (const float*)d_in[1];
    float* out = (float*)d_out;

    dim3 grid(IMG / TILE, IMG / TILE, NPLANES);
    ssim_tile_kernel<<<grid, 256>>>(clean, adv);
    finalize_kernel<<<1, 1>>>(out);
}